// round 15
// baseline (speedup 1.0000x reference)
#include <cuda_runtime.h>

#define NF      26
#define VOCAB   100000
#define EMBED   16
#define BATCH   16384
#define KDIM    16
#define NTOT    (NF * EMBED)   // 416
#define VSTRIDE 20             // [v0..v15, W, s2, pad, pad] -> conflict-free float4 LDS
#define ROWS    16             // rows per compute block
#define CTHREADS 128
#define GTHREADS 256
#define GITEMS  (BATCH * NF * 4)          // float4 items to gather = 1,703,936
#define GBLOCKS 1664                       // GBLOCKS*GTHREADS*4 == GITEMS

// 27.3 MB scratch for gathered embeddings, row-major [BATCH][NTOT].
__device__ float g_scratch[BATCH * NTOT];

// ---------------- Kernel A: fully parallel gather -> coalesced scratch ----------
__global__ __launch_bounds__(GTHREADS)
void fm_gather(const int* __restrict__ X,
               const float* __restrict__ tables)
{
    const int t = blockIdx.x * GTHREADS + threadIdx.x;
    const int stride = GBLOCKS * GTHREADS;             // 425,984
#pragma unroll
    for (int s = 0; s < 4; s++) {
        int item = t + s * stride;                     // < GITEMS by construction
        int row  = item / (NF * 4);
        int rest = item - row * (NF * 4);
        int f    = rest >> 2;
        int q    = rest & 3;
        int idx  = __ldg(&X[row * NF + f]);            // 4 threads share -> 1 request
        float4 ev = __ldg((const float4*)(tables
                         + ((long long)f * VOCAB + idx) * EMBED) + q);
        *((float4*)(g_scratch + row * NTOT + f * EMBED) + q) = ev;
    }
}

// ---------------- Kernel B: streaming compute (R7 structure, affine e loads) ----
extern __shared__ float smem[];

__global__ __launch_bounds__(CTHREADS, 6)
void fm_compute(const float* __restrict__ W,
                const float* __restrict__ bptr,
                const float* __restrict__ v,
                float* __restrict__ out)
{
    float* v_sh = smem;                                // [NTOT][VSTRIDE]

    const int tid = threadIdx.x;

    // Stage augmented tile: row n = [v[n][0..15], W[n], s2[n], 0, 0]
    for (int n = tid; n < NTOT; n += CTHREADS) {
        const float4* vr = (const float4*)(v + n * KDIM);
        float s2 = 0.f;
#pragma unroll
        for (int q = 0; q < 4; q++) {
            float4 a = vr[q];
            ((float4*)(v_sh + n * VSTRIDE))[q] = a;
            s2 += a.x * a.x + a.y * a.y + a.z * a.z + a.w * a.w;
        }
        v_sh[n * VSTRIDE + 16] = __ldg(&W[n]);
        v_sh[n * VSTRIDE + 17] = s2;
        v_sh[n * VSTRIDE + 18] = 0.f;
        v_sh[n * VSTRIDE + 19] = 0.f;
    }

    const int lane = tid & 31;
    const int j    = lane & 15;            // embedding component owned by this lane
    const int warp = tid >> 5;
    // Warp covers 4 rows: lanes 0-15 -> rows r0,r0+1 ; lanes 16-31 -> r0+2,r0+3.
    const int row0 = blockIdx.x * ROWS + warp * 4 + (lane >> 4) * 2;
    const float bval = __ldg(bptr);

    __syncthreads();

    float a0[KDIM], a1[KDIM];
#pragma unroll
    for (int k = 0; k < KDIM; k++) { a0[k] = 0.f; a1[k] = 0.f; }
    float lin0 = 0.f, lin1 = 0.f;          // partial sum_n e_n * W_n (this lane's j)
    float ss0  = 0.f, ss1  = 0.f;          // partial sum_n e_n^2 * s2_n

    const float* e0base = g_scratch + row0 * NTOT + j;        // affine, no idx hop
    const float* e1base = e0base + NTOT;

#pragma unroll
    for (int f = 0; f < NF; f++) {
        float e0 = __ldg(&e0base[f * EMBED]);  // independent, front-batchable
        float e1 = __ldg(&e1base[f * EMBED]);

        const float* rbase = v_sh + (f * EMBED + j) * VSTRIDE;
#pragma unroll
        for (int kq = 0; kq < 4; kq++) {
            float4 a = ((const float4*)rbase)[kq];
            a0[kq * 4 + 0] = fmaf(e0, a.x, a0[kq * 4 + 0]);
            a0[kq * 4 + 1] = fmaf(e0, a.y, a0[kq * 4 + 1]);
            a0[kq * 4 + 2] = fmaf(e0, a.z, a0[kq * 4 + 2]);
            a0[kq * 4 + 3] = fmaf(e0, a.w, a0[kq * 4 + 3]);
            a1[kq * 4 + 0] = fmaf(e1, a.x, a1[kq * 4 + 0]);
            a1[kq * 4 + 1] = fmaf(e1, a.y, a1[kq * 4 + 1]);
            a1[kq * 4 + 2] = fmaf(e1, a.z, a1[kq * 4 + 2]);
            a1[kq * 4 + 3] = fmaf(e1, a.w, a1[kq * 4 + 3]);
        }
        float4 ws = ((const float4*)rbase)[4];  // .x = W[n], .y = s2[n]
        lin0 = fmaf(e0,      ws.x, lin0);
        lin1 = fmaf(e1,      ws.x, lin1);
        ss0  = fmaf(e0 * e0, ws.y, ss0);
        ss1  = fmaf(e1 * e1, ws.y, ss1);
    }

    // Transpose-reduce across the 16-lane half: after 4 levels a0[0] holds a FULL
    // j-sum of one xv component (k-permutation harmless: final use is sum of
    // squares). 15 shfl per row. XOR offsets <= 8 stay inside the half.
#pragma unroll
    for (int off = 8; off >= 1; off >>= 1) {
#pragma unroll
        for (int i = 0; i < off; i++) {
            const int keep = (j & off) ? i + off : i;
            const int send = (j & off) ? i : i + off;
            float u0 = __shfl_xor_sync(0xffffffffu, a0[send], off);
            float u1 = __shfl_xor_sync(0xffffffffu, a1[send], off);
            a0[i] = a0[keep] + u0;
            a1[i] = a1[keep] + u1;
        }
    }

    // Per-lane scalar: 0.5*xv_k^2 (its k) + lin_partial - 0.5*ss_partial,
    // then one scalar butterfly over the half-warp.
    float c0 = fmaf(0.5f * a0[0], a0[0], fmaf(-0.5f, ss0, lin0));
    float c1 = fmaf(0.5f * a1[0], a1[0], fmaf(-0.5f, ss1, lin1));
#pragma unroll
    for (int off = 8; off >= 1; off >>= 1) {
        c0 += __shfl_xor_sync(0xffffffffu, c0, off);
        c1 += __shfl_xor_sync(0xffffffffu, c1, off);
    }

    if (j == 0) {
        float z0 = c0 + bval;
        float z1 = c1 + bval;
        out[row0]     = 1.f / (1.f + __expf(-z0));
        out[row0 + 1] = 1.f / (1.f + __expf(-z1));
    }
}

extern "C" void kernel_launch(void* const* d_in, const int* in_sizes, int n_in,
                              void* d_out, int out_size)
{
    const int*   X      = (const int*)d_in[0];
    const float* tables = (const float*)d_in[1];
    const float* W      = (const float*)d_in[2];
    const float* b      = (const float*)d_in[3];
    const float* v      = (const float*)d_in[4];
    float*       out    = (float*)d_out;

    fm_gather<<<GBLOCKS, GTHREADS>>>(X, tables);

    const size_t shmem = (size_t)NTOT * VSTRIDE * sizeof(float);   // 33280 B
    cudaFuncSetAttribute(fm_compute, cudaFuncAttributeMaxDynamicSharedMemorySize,
                         (int)shmem);
    fm_compute<<<BATCH / ROWS, CTHREADS, shmem>>>(W, b, v, out);
}

// round 16
// speedup vs baseline: 1.0034x; 1.0034x over previous
#include <cuda_runtime.h>

#define NF      26
#define VOCAB   100000
#define EMBED   16
#define BATCH   16384
#define KDIM    16
#define NTOT    (NF * EMBED)   // 416
#define VSTRIDE 20             // [v0..v15, W, s2, pad, pad] -> conflict-free float4 LDS
#define ROWS    16             // rows per block
#define THREADS 128

extern __shared__ float smem[];

__global__ __launch_bounds__(THREADS)
void fm_kernel(const int* __restrict__ X,
               const float* __restrict__ tables,
               const float* __restrict__ W,
               const float* __restrict__ bptr,
               const float* __restrict__ v,
               float* __restrict__ out)
{
    float* v_sh   = smem;                        // [NTOT][VSTRIDE]  33280 B
    int*   idx_sh = (int*)(smem + NTOT * VSTRIDE); // [ROWS][NF]     1664 B

    const int tid = threadIdx.x;

    // Stage augmented v tile: row n = [v[n][0..15], W[n], s2[n], 0, 0]
    for (int n = tid; n < NTOT; n += THREADS) {
        const float4* vr = (const float4*)(v + n * KDIM);
        float s2 = 0.f;
#pragma unroll
        for (int q = 0; q < 4; q++) {
            float4 a = vr[q];
            ((float4*)(v_sh + n * VSTRIDE))[q] = a;
            s2 += a.x * a.x + a.y * a.y + a.z * a.z + a.w * a.w;
        }
        v_sh[n * VSTRIDE + 16] = __ldg(&W[n]);
        v_sh[n * VSTRIDE + 17] = s2;
        v_sh[n * VSTRIDE + 18] = 0.f;
        v_sh[n * VSTRIDE + 19] = 0.f;
    }

    // Stage this block's X indices (coalesced; removes idx-LDG from the hot chain).
    const int base_row = blockIdx.x * ROWS;
    const int* xbase = X + base_row * NF;
    for (int i = tid; i < ROWS * NF; i += THREADS)
        idx_sh[i] = xbase[i];

    const int lane = tid & 31;
    const int j    = lane & 15;              // embedding component owned by this lane
    const int warp = tid >> 5;
    // Warp covers 4 rows: lanes 0-15 -> rows l0,l0+1 ; lanes 16-31 -> l0+2,l0+3.
    const int l0   = warp * 4 + (lane >> 4) * 2;
    const int row0 = base_row + l0;
    const float bval = __ldg(bptr);

    __syncthreads();

    float a0[KDIM], a1[KDIM];
#pragma unroll
    for (int k = 0; k < KDIM; k++) { a0[k] = 0.f; a1[k] = 0.f; }
    float lin0 = 0.f, lin1 = 0.f;            // partial sum_n e_n * W_n (this lane's j)
    float ss0  = 0.f, ss1  = 0.f;            // partial sum_n e_n^2 * s2_n

    const int* id0 = idx_sh + l0 * NF;       // uniform across half-warp -> LDS broadcast
    const int* id1 = id0 + NF;

    // Prologue: prefetch field 0's embeddings.
    float eA0, eA1;
    {
        int n0 = id0[0], n1 = id1[0];
        eA0 = __ldg(tables + (long long)n0 * EMBED + j);
        eA1 = __ldg(tables + (long long)n1 * EMBED + j);
    }

#pragma unroll
    for (int f = 0; f < NF; f++) {
        // Prefetch field f+1 (idx from smem -> immediate LDG issue).
        float eB0 = 0.f, eB1 = 0.f;
        if (f + 1 < NF) {
            int n0 = id0[f + 1], n1 = id1[f + 1];
            const float* base = tables + (long long)(f + 1) * VOCAB * EMBED;
            eB0 = __ldg(base + (long long)n0 * EMBED + j);
            eB1 = __ldg(base + (long long)n1 * EMBED + j);
        }

        const float* rbase = v_sh + (f * EMBED + j) * VSTRIDE;
#pragma unroll
        for (int kq = 0; kq < 4; kq++) {
            float4 a = ((const float4*)rbase)[kq];
            a0[kq * 4 + 0] = fmaf(eA0, a.x, a0[kq * 4 + 0]);
            a0[kq * 4 + 1] = fmaf(eA0, a.y, a0[kq * 4 + 1]);
            a0[kq * 4 + 2] = fmaf(eA0, a.z, a0[kq * 4 + 2]);
            a0[kq * 4 + 3] = fmaf(eA0, a.w, a0[kq * 4 + 3]);
            a1[kq * 4 + 0] = fmaf(eA1, a.x, a1[kq * 4 + 0]);
            a1[kq * 4 + 1] = fmaf(eA1, a.y, a1[kq * 4 + 1]);
            a1[kq * 4 + 2] = fmaf(eA1, a.z, a1[kq * 4 + 2]);
            a1[kq * 4 + 3] = fmaf(eA1, a.w, a1[kq * 4 + 3]);
        }
        float4 ws = ((const float4*)rbase)[4];   // .x = W[n], .y = s2[n]
        lin0 = fmaf(eA0,       ws.x, lin0);
        lin1 = fmaf(eA1,       ws.x, lin1);
        ss0  = fmaf(eA0 * eA0, ws.y, ss0);
        ss1  = fmaf(eA1 * eA1, ws.y, ss1);

        eA0 = eB0;
        eA1 = eB1;
    }

    // Transpose-reduce across the 16-lane half: after 4 levels a0[0] holds a FULL
    // j-sum of one xv component (k-permutation harmless: final use is sum of
    // squares). 15 shfl per row. XOR offsets <= 8 stay inside the half.
#pragma unroll
    for (int off = 8; off >= 1; off >>= 1) {
#pragma unroll
        for (int i = 0; i < off; i++) {
            const int keep = (j & off) ? i + off : i;
            const int send = (j & off) ? i : i + off;
            float u0 = __shfl_xor_sync(0xffffffffu, a0[send], off);
            float u1 = __shfl_xor_sync(0xffffffffu, a1[send], off);
            a0[i] = a0[keep] + u0;
            a1[i] = a1[keep] + u1;
        }
    }

    // Per-lane scalar: 0.5*xv_k^2 (its k) + lin_partial - 0.5*ss_partial,
    // then one scalar butterfly over the half-warp.
    float c0 = fmaf(0.5f * a0[0], a0[0], fmaf(-0.5f, ss0, lin0));
    float c1 = fmaf(0.5f * a1[0], a1[0], fmaf(-0.5f, ss1, lin1));
#pragma unroll
    for (int off = 8; off >= 1; off >>= 1) {
        c0 += __shfl_xor_sync(0xffffffffu, c0, off);
        c1 += __shfl_xor_sync(0xffffffffu, c1, off);
    }

    if (j == 0) {
        float z0 = c0 + bval;
        float z1 = c1 + bval;
        out[row0]     = 1.f / (1.f + __expf(-z0));
        out[row0 + 1] = 1.f / (1.f + __expf(-z1));
    }
}

extern "C" void kernel_launch(void* const* d_in, const int* in_sizes, int n_in,
                              void* d_out, int out_size)
{
    const int*   X      = (const int*)d_in[0];
    const float* tables = (const float*)d_in[1];
    const float* W      = (const float*)d_in[2];
    const float* b      = (const float*)d_in[3];
    const float* v      = (const float*)d_in[4];
    float*       out    = (float*)d_out;

    const size_t shmem = (size_t)NTOT * VSTRIDE * sizeof(float)
                       + (size_t)ROWS * NF * sizeof(int);   // 34944 B
    cudaFuncSetAttribute(fm_kernel, cudaFuncAttributeMaxDynamicSharedMemorySize,
                         (int)shmem);

    // 16 rows per block (4 warps x 4 rows), 1024 blocks covers BATCH=16384.
    fm_kernel<<<BATCH / ROWS, THREADS, shmem>>>(X, tables, W, b, v, out);
}

// round 17
// speedup vs baseline: 1.4955x; 1.4904x over previous
#include <cuda_runtime.h>
#include <cstdint>

#define NF      26
#define VOCAB   100000
#define EMBED   16
#define BATCH   16384
#define KDIM    16
#define NTOT    (NF * EMBED)   // 416
#define ROWS    16             // rows per block
#define THREADS 128

// v tile: dense 64B rows with SW64 swizzle -> conflict-free LDS.128, no padding.
// ws array: (W[n], s2[n]) pairs, broadcast reads.
// total smem = 416*64 + 416*8 = 26624 + 3328 = 29952 B  -> 7 CTAs/SM (single wave)

extern __shared__ float smem[];

__global__ __launch_bounds__(THREADS, 7)
void fm_kernel(const int* __restrict__ X,
               const float* __restrict__ tables,
               const float* __restrict__ W,
               const float* __restrict__ bptr,
               const float* __restrict__ v,
               float* __restrict__ out)
{
    float*  v_sh  = smem;                          // [NTOT][16] swizzled, 26624 B
    float2* ws_sh = (float2*)(smem + NTOT * EMBED); // [NTOT], 3328 B

    const int tid = threadIdx.x;

    // Stage v tile (SW64 swizzle) + (W, s2) pairs.
    for (int n = tid; n < NTOT; n += THREADS) {
        const float4* vr = (const float4*)(v + n * KDIM);
        float s2 = 0.f;
#pragma unroll
        for (int q = 0; q < 4; q++) {
            float4 a = vr[q];
            uint32_t off = ((uint32_t)n << 6) + ((uint32_t)q << 4);
            off ^= (off >> 3) & 0x30;              // SW64 swizzle
            *(float4*)((char*)v_sh + off) = a;
            s2 += a.x * a.x + a.y * a.y + a.z * a.z + a.w * a.w;
        }
        ws_sh[n] = make_float2(__ldg(&W[n]), s2);
    }

    const int lane = tid & 31;
    const int j    = lane & 15;              // embedding component owned by this lane
    const int warp = tid >> 5;
    // Warp covers 4 rows: lanes 0-15 -> rows r0,r0+1 ; lanes 16-31 -> r0+2,r0+3.
    const int row0 = blockIdx.x * ROWS + warp * 4 + (lane >> 4) * 2;
    const int row1 = row0 + 1;
    const float bval = __ldg(bptr);
    const int t = (j >> 1) & 3;              // lane-constant quadrant permutation

    __syncthreads();

    float a0[KDIM], a1[KDIM];
#pragma unroll
    for (int k = 0; k < KDIM; k++) { a0[k] = 0.f; a1[k] = 0.f; }
    float lin0 = 0.f, lin1 = 0.f;            // partial sum_n e_n * W_n (this lane's j)
    float ss0  = 0.f, ss1  = 0.f;            // partial sum_n e_n^2 * s2_n

    const int* xrow0 = X + row0 * NF;
    const int* xrow1 = X + row1 * NF;

#pragma unroll
    for (int f = 0; f < NF; f++) {
        int idx0 = __ldg(&xrow0[f]);         // uniform across half-warp -> broadcast
        int idx1 = __ldg(&xrow1[f]);
        const float* base = tables + (long long)f * VOCAB * EMBED;
        float e0 = __ldg(base + (long long)idx0 * EMBED + j);  // half-warp = one 64B line
        float e1 = __ldg(base + (long long)idx1 * EMBED + j);

        const int n = f * EMBED + j;
        const float4* rbase = (const float4*)((const char*)v_sh + (n << 6));
#pragma unroll
        for (int kq = 0; kq < 4; kq++) {
            float4 a = rbase[kq ^ t];        // SW64: per-lane fixed permutation
            a0[kq * 4 + 0] = fmaf(e0, a.x, a0[kq * 4 + 0]);
            a0[kq * 4 + 1] = fmaf(e0, a.y, a0[kq * 4 + 1]);
            a0[kq * 4 + 2] = fmaf(e0, a.z, a0[kq * 4 + 2]);
            a0[kq * 4 + 3] = fmaf(e0, a.w, a0[kq * 4 + 3]);
            a1[kq * 4 + 0] = fmaf(e1, a.x, a1[kq * 4 + 0]);
            a1[kq * 4 + 1] = fmaf(e1, a.y, a1[kq * 4 + 1]);
            a1[kq * 4 + 2] = fmaf(e1, a.z, a1[kq * 4 + 2]);
            a1[kq * 4 + 3] = fmaf(e1, a.w, a1[kq * 4 + 3]);
        }
        float2 ws = ws_sh[n];                // .x = W[n], .y = s2[n]
        lin0 = fmaf(e0,      ws.x, lin0);
        lin1 = fmaf(e1,      ws.x, lin1);
        ss0  = fmaf(e0 * e0, ws.y, ss0);
        ss1  = fmaf(e1 * e1, ws.y, ss1);
    }

    // Transpose-reduce across the 16-lane half: after 4 levels a0[0] holds a FULL
    // j-sum of one xv component. The k-permutation (swizzle + tree) is harmless:
    // the only use is the sum of squares. 15 shfl per row; XOR offsets <= 8 stay
    // inside the half-warp.
#pragma unroll
    for (int off = 8; off >= 1; off >>= 1) {
#pragma unroll
        for (int i = 0; i < off; i++) {
            const int keep = (j & off) ? i + off : i;
            const int send = (j & off) ? i : i + off;
            float u0 = __shfl_xor_sync(0xffffffffu, a0[send], off);
            float u1 = __shfl_xor_sync(0xffffffffu, a1[send], off);
            a0[i] = a0[keep] + u0;
            a1[i] = a1[keep] + u1;
        }
    }

    // Per-lane scalar: 0.5*xv_k^2 (its k) + lin_partial - 0.5*ss_partial,
    // then one scalar butterfly over the half-warp.
    float c0 = fmaf(0.5f * a0[0], a0[0], fmaf(-0.5f, ss0, lin0));
    float c1 = fmaf(0.5f * a1[0], a1[0], fmaf(-0.5f, ss1, lin1));
#pragma unroll
    for (int off = 8; off >= 1; off >>= 1) {
        c0 += __shfl_xor_sync(0xffffffffu, c0, off);
        c1 += __shfl_xor_sync(0xffffffffu, c1, off);
    }

    if (j == 0) {
        float z0 = c0 + bval;
        float z1 = c1 + bval;
        out[row0] = 1.f / (1.f + __expf(-z0));
        out[row1] = 1.f / (1.f + __expf(-z1));
    }
}

extern "C" void kernel_launch(void* const* d_in, const int* in_sizes, int n_in,
                              void* d_out, int out_size)
{
    const int*   X      = (const int*)d_in[0];
    const float* tables = (const float*)d_in[1];
    const float* W      = (const float*)d_in[2];
    const float* b      = (const float*)d_in[3];
    const float* v      = (const float*)d_in[4];
    float*       out    = (float*)d_out;

    const size_t shmem = (size_t)NTOT * EMBED * sizeof(float)
                       + (size_t)NTOT * sizeof(float2);      // 29952 B
    cudaFuncSetAttribute(fm_kernel, cudaFuncAttributeMaxDynamicSharedMemorySize,
                         (int)shmem);

    // 16 rows per block (4 warps x 4 rows), 1024 blocks covers BATCH=16384.
    // 29.95 KB smem + <=73 regs -> 7 CTAs/SM -> 1036 concurrent CTAs: single wave.
    fm_kernel<<<BATCH / ROWS, THREADS, shmem>>>(X, tables, W, b, v, out);
}